// round 16
// baseline (speedup 1.0000x reference)
#include <cuda_runtime.h>
#include <math.h>

#define THREADS 128
#define OBS 127

typedef unsigned long long u64;

__device__ __forceinline__ u64 ffma2(u64 a, u64 b, u64 c) {
  u64 d; asm("fma.rn.f32x2 %0, %1, %2, %3;" : "=l"(d) : "l"(a), "l"(b), "l"(c)); return d;
}
__device__ __forceinline__ u64 fmul2(u64 a, u64 b) {
  u64 d; asm("mul.rn.f32x2 %0, %1, %2;" : "=l"(d) : "l"(a), "l"(b)); return d;
}
__device__ __forceinline__ u64 fadd2(u64 a, u64 b) {
  u64 d; asm("add.rn.f32x2 %0, %1, %2;" : "=l"(d) : "l"(a), "l"(b)); return d;
}
__device__ __forceinline__ u64 pack2(float lo, float hi) {
  u64 d; asm("mov.b64 %0, {%1, %2};" : "=l"(d) : "f"(lo), "f"(hi)); return d;
}
__device__ __forceinline__ void unpack2(u64 v, float& lo, float& hi) {
  asm("mov.b64 {%0, %1}, %2;" : "=f"(lo), "=f"(hi) : "l"(v));
}
__device__ __forceinline__ u64 bcast2(float x) { return pack2(x, x); }
__device__ __forceinline__ u64 relu2(u64 v) {
  float a, b; unpack2(v, a, b);
  return pack2(fmaxf(a, 0.0f), fmaxf(b, 0.0f));
}
// leaky_relu(x) = 0.505*x + 0.495*|x| (exact for slope 0.01), packed.
__device__ __forceinline__ u64 leaky2(u64 v) {
  const u64 absv = v & 0x7FFFFFFF7FFFFFFFULL;
  return ffma2(bcast2(0.505f), v, fmul2(bcast2(0.495f), absv));
}

// ---------------- constant blob: raw tensor layouts (float offsets) ----------------
enum {
  EN_W1 = 0,      // [4][32]
  EN_B1 = 128,    // [32]
  EN_W2 = 160,    // [32][16]
  EN_B2 = 672,    // [16]
  OA_W1 = 688,    // [5][32]
  OA_B1 = 848,    // [32]
  OA_W2 = 880,    // [32][16]
  OA_B2 = 1392,   // [16]
  OA_G  = 1408,   // [16]
  OA_BLN= 1424,   // [16]
  G_W1  = 1440,   // [3][32]
  G_B1  = 1536,   // [32]
  G_W2  = 1568,   // [32][16]
  G_B2  = 2080,   // [16]
  G_G   = 2096,   // [16]
  G_BLN = 2112,   // [16]
  M_W1  = 2128,   // [48][32]
  M_B1  = 3664,   // [32]
  M_W2  = 3696,   // [32][32]
  M_B2  = 4720,   // [32]
  M_W3  = 4752,   // [32][2]
  M_B3  = 4816,   // [2]
  CW_TOTAL = 4818
};
__constant__ float cw[CW_TOTAL];
__device__ float dw_stage[CW_TOTAL];      // staging for single-symbol-copy upload
__device__ __forceinline__ u64 c2(int off) { return *(const u64*)(cw + off); }

// Gather all 22 weight tensors into the staging blob in one kernel.
__global__ void pack_weights(
    const float* p1,  const float* p2,  const float* p3,  const float* p4,
    const float* p5,  const float* p6,  const float* p7,  const float* p8,
    const float* p9,  const float* p10, const float* p11, const float* p12,
    const float* p13, const float* p14, const float* p15, const float* p16,
    const float* p17, const float* p18, const float* p19, const float* p20,
    const float* p21, const float* p22)
{
  const int t = threadIdx.x;
  #define SEG(off, src, n) for (int i = t; i < (n); i += 256) dw_stage[(off) + i] = (src)[i];
  SEG(EN_W1, p1, 128)  SEG(EN_B1, p2, 32)
  SEG(EN_W2, p3, 512)  SEG(EN_B2, p4, 16)
  SEG(OA_W1, p5, 160)  SEG(OA_B1, p6, 32)
  SEG(OA_W2, p7, 512)  SEG(OA_B2, p8, 16)
  SEG(OA_G,  p9, 16)   SEG(OA_BLN, p10, 16)
  SEG(G_W1,  p11, 96)  SEG(G_B1, p12, 32)
  SEG(G_W2,  p13, 512) SEG(G_B2, p14, 16)
  SEG(G_G,   p15, 16)  SEG(G_BLN, p16, 16)
  SEG(M_W1,  p17, 1536) SEG(M_B1, p18, 32)
  SEG(M_W2,  p19, 1024) SEG(M_B2, p20, 32)
  SEG(M_W3,  p21, 64)  SEG(M_B3, p22, 2)
  #undef SEG
}

// ---------------- smem: weight mirror + per-thread otherp/selfp stashes ----------------
enum {
  EN_W2S = 0,     // [32][16]
  OA_W2S = 512,   // [32][16]
  G_W2S  = 1024,  // [32][16]
  M_W1S  = 1536,  // [48][32]
  M_W2S  = 3072,  // [32][32]
  STASH_O = 4096,                    // otherp: 128 thr * 16 floats
  STASH_S = 4096 + THREADS * 16,     // selfp:  128 thr * 16 floats
  SW_TOTAL = 4096 + THREADS * 32
};

__global__ void __launch_bounds__(THREADS, 5)
actor_kernel(const float* __restrict__ s_input,
             const float* __restrict__ en_w2g, const float* __restrict__ oa_w2g,
             const float* __restrict__ g_w2g,  const float* __restrict__ m_w1g,
             const float* __restrict__ m_w2g,
             float* __restrict__ out, int B)
{
  __shared__ float sw[SW_TOTAL];
  const int tid = threadIdx.x;
  #define CP(off, src, n) \
    for (int i = tid; i < (n); i += THREADS) sw[(off) + i] = (src)[i];
  CP(EN_W2S, en_w2g, 512)
  CP(OA_W2S, oa_w2g, 512)
  CP(G_W2S,  g_w2g,  512)
  CP(M_W1S,  m_w1g,  1536)
  CP(M_W2S,  m_w2g,  1024)
  #undef CP
  __syncthreads();

  const int b = blockIdx.x * THREADS + tid;
  if (b >= B) return;
  const float* __restrict__ s = s_input + (size_t)b * OBS;
  u64* const stash_o = (u64*)&sw[STASH_O + tid * 16];
  u64* const stash_s = (u64*)&sw[STASH_S + tid * 16];

  // Layer-2 row apply, SINGLE entity: cols 0..3 const, 4..15 smem.
  #define L2ROW1(A, CBASE, SBASE, ROW)                                      \
    {                                                                       \
      ea[0] = ffma2(A, c2((CBASE) + (ROW) * 16 + 0), ea[0]);                \
      ea[1] = ffma2(A, c2((CBASE) + (ROW) * 16 + 2), ea[1]);                \
      const ulonglong2* wh = (const ulonglong2*)&sw[(SBASE) + (ROW) * 16 + 4]; \
      ulonglong2 v0 = wh[0], v1 = wh[1], v2 = wh[2];                        \
      ea[2] = ffma2(A, v0.x, ea[2]); ea[3] = ffma2(A, v0.y, ea[3]);         \
      ea[4] = ffma2(A, v1.x, ea[4]); ea[5] = ffma2(A, v1.y, ea[5]);         \
      ea[6] = ffma2(A, v2.x, ea[6]); ea[7] = ffma2(A, v2.y, ea[7]);         \
    }

  // Layer-2 row apply, PAIR of entities: weights fetched ONCE, applied twice.
  #define L2ROW2(Aa, Ab, CBASE, SBASE, ROW)                                 \
    {                                                                       \
      u64 cwa = c2((CBASE) + (ROW) * 16 + 0), cwb = c2((CBASE) + (ROW) * 16 + 2); \
      ea[0] = ffma2(Aa, cwa, ea[0]); eb[0] = ffma2(Ab, cwa, eb[0]);         \
      ea[1] = ffma2(Aa, cwb, ea[1]); eb[1] = ffma2(Ab, cwb, eb[1]);         \
      const ulonglong2* wh = (const ulonglong2*)&sw[(SBASE) + (ROW) * 16 + 4]; \
      ulonglong2 v0 = wh[0], v1 = wh[1], v2 = wh[2];                        \
      ea[2] = ffma2(Aa, v0.x, ea[2]); eb[2] = ffma2(Ab, v0.x, eb[2]);       \
      ea[3] = ffma2(Aa, v0.y, ea[3]); eb[3] = ffma2(Ab, v0.y, eb[3]);       \
      ea[4] = ffma2(Aa, v1.x, ea[4]); eb[4] = ffma2(Ab, v1.x, eb[4]);       \
      ea[5] = ffma2(Aa, v1.y, ea[5]); eb[5] = ffma2(Ab, v1.y, eb[5]);       \
      ea[6] = ffma2(Aa, v2.x, ea[6]); eb[6] = ffma2(Ab, v2.x, eb[6]);       \
      ea[7] = ffma2(Aa, v2.y, ea[7]); eb[7] = ffma2(Ab, v2.y, eb[7]);       \
    }

  // Layer-2 row apply, TRIPLE of entities.
  #define L2ROW3(Aa, Ab, Ac, CBASE, SBASE, ROW)                             \
    {                                                                       \
      u64 cwa = c2((CBASE) + (ROW) * 16 + 0), cwb = c2((CBASE) + (ROW) * 16 + 2); \
      ea[0] = ffma2(Aa, cwa, ea[0]); eb[0] = ffma2(Ab, cwa, eb[0]); ec[0] = ffma2(Ac, cwa, ec[0]); \
      ea[1] = ffma2(Aa, cwb, ea[1]); eb[1] = ffma2(Ab, cwb, eb[1]); ec[1] = ffma2(Ac, cwb, ec[1]); \
      const ulonglong2* wh = (const ulonglong2*)&sw[(SBASE) + (ROW) * 16 + 4]; \
      ulonglong2 v0 = wh[0], v1 = wh[1], v2 = wh[2];                        \
      ea[2] = ffma2(Aa, v0.x, ea[2]); eb[2] = ffma2(Ab, v0.x, eb[2]); ec[2] = ffma2(Ac, v0.x, ec[2]); \
      ea[3] = ffma2(Aa, v0.y, ea[3]); eb[3] = ffma2(Ab, v0.y, eb[3]); ec[3] = ffma2(Ac, v0.y, ec[3]); \
      ea[4] = ffma2(Aa, v1.x, ea[4]); eb[4] = ffma2(Ab, v1.x, eb[4]); ec[4] = ffma2(Ac, v1.x, ec[4]); \
      ea[5] = ffma2(Aa, v1.y, ea[5]); eb[5] = ffma2(Ab, v1.y, eb[5]); ec[5] = ffma2(Ac, v1.y, ec[5]); \
      ea[6] = ffma2(Aa, v2.x, ea[6]); eb[6] = ffma2(Ab, v2.x, eb[6]); ec[6] = ffma2(Ac, v2.x, ec[6]); \
      ea[7] = ffma2(Aa, v2.y, ea[7]); eb[7] = ffma2(Ab, v2.y, eb[7]); ec[7] = ffma2(Ac, v2.y, ec[7]); \
    }

  // Softmax update with selfp in REGISTERS (OA branch).
  #define SM_UPDATE(earr)                                                   \
    {                                                                       \
      _Pragma("unroll")                                                     \
      for (int t = 0; t < 8; t++) earr[t] = relu2(earr[t]);                 \
      u64 sc2a = 0ULL, sc2b = 0ULL;                                         \
      _Pragma("unroll")                                                     \
      for (int t = 0; t < 4; t++) {                                         \
        sc2a = ffma2(selfp[2*t],     earr[2*t],     sc2a);                  \
        sc2b = ffma2(selfp[2*t + 1], earr[2*t + 1], sc2b);                  \
      }                                                                     \
      const u64 sc2 = fadd2(sc2a, sc2b);                                    \
      float slo, shi; unpack2(sc2, slo, shi);                               \
      const float pe = __expf((slo + shi) * 0.25f);                         \
      dd += pe;                                                             \
      const u64 P = bcast2(pe);                                             \
      _Pragma("unroll")                                                     \
      for (int t = 0; t < 8; t++) acc[t] = ffma2(P, earr[t], acc[t]);       \
    }

  // Softmax update with selfp read from the smem stash (food branch).
  #define SM_UPDATE_S(earr)                                                 \
    {                                                                       \
      _Pragma("unroll")                                                     \
      for (int t = 0; t < 8; t++) earr[t] = relu2(earr[t]);                 \
      const ulonglong2* sp2 = (const ulonglong2*)stash_s;                   \
      ulonglong2 s0 = sp2[0], s1 = sp2[1], s2 = sp2[2], s3 = sp2[3];        \
      u64 sc2a = 0ULL, sc2b = 0ULL;                                         \
      sc2a = ffma2(s0.x, earr[0], sc2a); sc2b = ffma2(s0.y, earr[1], sc2b); \
      sc2a = ffma2(s1.x, earr[2], sc2a); sc2b = ffma2(s1.y, earr[3], sc2b); \
      sc2a = ffma2(s2.x, earr[4], sc2a); sc2b = ffma2(s2.y, earr[5], sc2b); \
      sc2a = ffma2(s3.x, earr[6], sc2a); sc2b = ffma2(s3.y, earr[7], sc2b); \
      const u64 sc2 = fadd2(sc2a, sc2b);                                    \
      float slo, shi; unpack2(sc2, slo, shi);                               \
      const float pe = __expf((slo + shi) * 0.25f);                         \
      dd += pe;                                                             \
      const u64 P = bcast2(pe);                                             \
      _Pragma("unroll")                                                     \
      for (int t = 0; t < 8; t++) acc[t] = ffma2(P, earr[t], acc[t]);       \
    }

  // LayerNorm + relu epilogue from acc/dd into dst.
  #define LN_EPILOGUE(dst, GOFF, BLNOFF)                                    \
    {                                                                       \
      const u64 INV = bcast2(1.0f / dd);                                    \
      float att[16], mu = 0.0f;                                             \
      _Pragma("unroll")                                                     \
      for (int t = 0; t < 8; t++) {                                         \
        acc[t] = fmul2(acc[t], INV);                                        \
        float a0, a1; unpack2(acc[t], a0, a1);                              \
        att[2*t] = a0; att[2*t+1] = a1;                                     \
        mu += a0 + a1;                                                      \
      }                                                                     \
      mu *= (1.0f / 16.0f);                                                 \
      float var = 0.0f;                                                     \
      _Pragma("unroll")                                                     \
      for (int k = 0; k < 16; k++) { const float t = att[k] - mu; var = fmaf(t, t, var); } \
      var *= (1.0f / 16.0f);                                                \
      const float isd = rsqrtf(var + 1e-5f);                                \
      _Pragma("unroll")                                                     \
      for (int t = 0; t < 8; t++) {                                         \
        const u64 y = pack2((att[2*t] - mu) * isd, (att[2*t+1] - mu) * isd);\
        dst[t] = relu2(ffma2(y, c2((GOFF) + 2*t), c2((BLNOFF) + 2*t)));     \
      }                                                                     \
    }

  // ================= self MLP: 4 -> 32 -> 16 =================
  u64 selfp[8];
  {
    u64 ea[8];
    #pragma unroll
    for (int t = 0; t < 8; t++) ea[t] = c2(EN_B2 + 2 * t);
    const u64 p0 = bcast2(s[0]), p1 = bcast2(s[1]), p2 = bcast2(s[2]), p3 = bcast2(s[3]);
    #pragma unroll 4
    for (int jp = 0; jp < 16; jp++) {
      u64 a = c2(EN_B1 + 2 * jp);
      a = ffma2(p0, c2(EN_W1 +      2 * jp), a);
      a = ffma2(p1, c2(EN_W1 + 32 + 2 * jp), a);
      a = ffma2(p2, c2(EN_W1 + 64 + 2 * jp), a);
      a = ffma2(p3, c2(EN_W1 + 96 + 2 * jp), a);
      float a0, a1; unpack2(a, a0, a1);
      const u64 A0 = bcast2(fmaxf(a0, 0.0f));
      const u64 A1 = bcast2(fmaxf(a1, 0.0f));
      L2ROW1(A0, EN_W2, EN_W2S, 2 * jp)
      L2ROW1(A1, EN_W2, EN_W2S, 2 * jp + 1)
    }
    #pragma unroll
    for (int t = 0; t < 8; t++) selfp[t] = relu2(ea[t]);
  }

  // ================= other-agent branch: 15 entities = 7 pairs + 1 =================
  {
    float dd = 0.0f;
    u64 acc[8];
    #pragma unroll
    for (int t = 0; t < 8; t++) acc[t] = 0ULL;

    #pragma unroll 1
    for (int q = 0; q < 7; q++) {
      const int n = 2 * q;
      const u64 pa0 = bcast2(s[4 + 2*n]),  pb0 = bcast2(s[6 + 2*n]);
      const u64 pa1 = bcast2(s[5 + 2*n]),  pb1 = bcast2(s[7 + 2*n]);
      const u64 pa2 = bcast2(s[34 + 2*n]), pb2 = bcast2(s[36 + 2*n]);
      const u64 pa3 = bcast2(s[35 + 2*n]), pb3 = bcast2(s[37 + 2*n]);
      const u64 pa4 = bcast2(s[64 + n]),   pb4 = bcast2(s[65 + n]);

      u64 ea[8], eb[8];
      #pragma unroll
      for (int t = 0; t < 8; t++) { u64 bb = c2(OA_B2 + 2 * t); ea[t] = bb; eb[t] = bb; }

      #pragma unroll 2
      for (int jp = 0; jp < 16; jp++) {
        const u64 kb = c2(OA_B1 + 2 * jp);
        const u64 k0 = c2(OA_W1 +       2 * jp);
        const u64 k1 = c2(OA_W1 + 32  + 2 * jp);
        const u64 k2 = c2(OA_W1 + 64  + 2 * jp);
        const u64 k3 = c2(OA_W1 + 96  + 2 * jp);
        const u64 k4 = c2(OA_W1 + 128 + 2 * jp);
        u64 aa = kb;
        aa = ffma2(pa0, k0, aa); aa = ffma2(pa1, k1, aa); aa = ffma2(pa2, k2, aa);
        aa = ffma2(pa3, k3, aa); aa = ffma2(pa4, k4, aa);
        u64 ab = kb;
        ab = ffma2(pb0, k0, ab); ab = ffma2(pb1, k1, ab); ab = ffma2(pb2, k2, ab);
        ab = ffma2(pb3, k3, ab); ab = ffma2(pb4, k4, ab);
        float x0, x1; unpack2(aa, x0, x1);
        const u64 Aa0 = bcast2(fmaxf(x0, 0.0f));
        const u64 Aa1 = bcast2(fmaxf(x1, 0.0f));
        unpack2(ab, x0, x1);
        const u64 Ab0 = bcast2(fmaxf(x0, 0.0f));
        const u64 Ab1 = bcast2(fmaxf(x1, 0.0f));
        L2ROW2(Aa0, Ab0, OA_W2, OA_W2S, 2 * jp)
        L2ROW2(Aa1, Ab1, OA_W2, OA_W2S, 2 * jp + 1)
      }
      SM_UPDATE(ea)
      SM_UPDATE(eb)
    }
    { // tail entity n = 14
      const int n = 14;
      const u64 p0 = bcast2(s[4 + 2*n]);
      const u64 p1 = bcast2(s[5 + 2*n]);
      const u64 p2 = bcast2(s[34 + 2*n]);
      const u64 p3 = bcast2(s[35 + 2*n]);
      const u64 p4 = bcast2(s[64 + n]);
      u64 ea[8];
      #pragma unroll
      for (int t = 0; t < 8; t++) ea[t] = c2(OA_B2 + 2 * t);
      #pragma unroll 2
      for (int jp = 0; jp < 16; jp++) {
        u64 a = c2(OA_B1 + 2 * jp);
        a = ffma2(p0, c2(OA_W1 +       2 * jp), a);
        a = ffma2(p1, c2(OA_W1 + 32  + 2 * jp), a);
        a = ffma2(p2, c2(OA_W1 + 64  + 2 * jp), a);
        a = ffma2(p3, c2(OA_W1 + 96  + 2 * jp), a);
        a = ffma2(p4, c2(OA_W1 + 128 + 2 * jp), a);
        float x0, x1; unpack2(a, x0, x1);
        const u64 A0 = bcast2(fmaxf(x0, 0.0f));
        const u64 A1 = bcast2(fmaxf(x1, 0.0f));
        L2ROW1(A0, OA_W2, OA_W2S, 2 * jp)
        L2ROW1(A1, OA_W2, OA_W2S, 2 * jp + 1)
      }
      SM_UPDATE(ea)
    }
    u64 otherp[8];
    LN_EPILOGUE(otherp, OA_G, OA_BLN)
    #pragma unroll
    for (int t = 0; t < 8; t++) stash_o[t] = otherp[t];
  }

  // selfp is no longer needed in registers: stash it for the food loop + merge.
  #pragma unroll
  for (int t = 0; t < 8; t++) stash_s[t] = selfp[t];

  // ================= food branch: 16 entities = 5 triples + 1 =================
  u64 foodp[8];
  {
    float dd = 0.0f;
    u64 acc[8];
    #pragma unroll
    for (int t = 0; t < 8; t++) acc[t] = 0ULL;

    #pragma unroll 1
    for (int q = 0; q < 5; q++) {
      const int n = 3 * q;
      const u64 pa0 = bcast2(s[79 + 3*n]), pb0 = bcast2(s[82 + 3*n]), pc0 = bcast2(s[85 + 3*n]);
      const u64 pa1 = bcast2(s[80 + 3*n]), pb1 = bcast2(s[83 + 3*n]), pc1 = bcast2(s[86 + 3*n]);
      const u64 pa2 = bcast2(s[81 + 3*n]), pb2 = bcast2(s[84 + 3*n]), pc2 = bcast2(s[87 + 3*n]);

      u64 ea[8], eb[8], ec[8];
      #pragma unroll
      for (int t = 0; t < 8; t++) { u64 bb = c2(G_B2 + 2 * t); ea[t] = bb; eb[t] = bb; ec[t] = bb; }

      #pragma unroll 2
      for (int jp = 0; jp < 16; jp++) {
        const u64 kb = c2(G_B1 + 2 * jp);
        const u64 k0 = c2(G_W1 +      2 * jp);
        const u64 k1 = c2(G_W1 + 32 + 2 * jp);
        const u64 k2 = c2(G_W1 + 64 + 2 * jp);
        u64 aa = kb;
        aa = ffma2(pa0, k0, aa); aa = ffma2(pa1, k1, aa); aa = ffma2(pa2, k2, aa);
        u64 ab = kb;
        ab = ffma2(pb0, k0, ab); ab = ffma2(pb1, k1, ab); ab = ffma2(pb2, k2, ab);
        u64 ac = kb;
        ac = ffma2(pc0, k0, ac); ac = ffma2(pc1, k1, ac); ac = ffma2(pc2, k2, ac);
        float x0, x1; unpack2(aa, x0, x1);
        const u64 Aa0 = bcast2(fmaxf(x0, 0.0f));
        const u64 Aa1 = bcast2(fmaxf(x1, 0.0f));
        unpack2(ab, x0, x1);
        const u64 Ab0 = bcast2(fmaxf(x0, 0.0f));
        const u64 Ab1 = bcast2(fmaxf(x1, 0.0f));
        unpack2(ac, x0, x1);
        const u64 Ac0 = bcast2(fmaxf(x0, 0.0f));
        const u64 Ac1 = bcast2(fmaxf(x1, 0.0f));
        L2ROW3(Aa0, Ab0, Ac0, G_W2, G_W2S, 2 * jp)
        L2ROW3(Aa1, Ab1, Ac1, G_W2, G_W2S, 2 * jp + 1)
      }
      SM_UPDATE_S(ea)
      SM_UPDATE_S(eb)
      SM_UPDATE_S(ec)
    }
    { // tail entity n = 15
      const u64 p0 = bcast2(s[124]);
      const u64 p1 = bcast2(s[125]);
      const u64 p2 = bcast2(s[126]);
      u64 ea[8];
      #pragma unroll
      for (int t = 0; t < 8; t++) ea[t] = c2(G_B2 + 2 * t);
      #pragma unroll 2
      for (int jp = 0; jp < 16; jp++) {
        u64 a = c2(G_B1 + 2 * jp);
        a = ffma2(p0, c2(G_W1 +      2 * jp), a);
        a = ffma2(p1, c2(G_W1 + 32 + 2 * jp), a);
        a = ffma2(p2, c2(G_W1 + 64 + 2 * jp), a);
        float x0, x1; unpack2(a, x0, x1);
        const u64 A0 = bcast2(fmaxf(x0, 0.0f));
        const u64 A1 = bcast2(fmaxf(x1, 0.0f));
        L2ROW1(A0, G_W2, G_W2S, 2 * jp)
        L2ROW1(A1, G_W2, G_W2S, 2 * jp + 1)
      }
      SM_UPDATE_S(ea)
    }
    LN_EPILOGUE(foodp, G_G, G_BLN)
  }

  // Merge-layer row apply: outputs 0..7 const, outputs 8..31 smem.
  #define MROW_APPLY(V, CBASE, SBASE, ROW, H)                               \
    {                                                                       \
      H[0] = ffma2(V, c2((CBASE) + (ROW) * 32 + 0), H[0]);                  \
      H[1] = ffma2(V, c2((CBASE) + (ROW) * 32 + 2), H[1]);                  \
      H[2] = ffma2(V, c2((CBASE) + (ROW) * 32 + 4), H[2]);                  \
      H[3] = ffma2(V, c2((CBASE) + (ROW) * 32 + 6), H[3]);                  \
      const ulonglong2* wh = (const ulonglong2*)&sw[(SBASE) + (ROW) * 32 + 8]; \
      ulonglong2 w0 = wh[0], w1 = wh[1], w2 = wh[2],                        \
                 w3 = wh[3], w4 = wh[4], w5 = wh[5];                        \
      H[4]  = ffma2(V, w0.x, H[4]);  H[5]  = ffma2(V, w0.y, H[5]);          \
      H[6]  = ffma2(V, w1.x, H[6]);  H[7]  = ffma2(V, w1.y, H[7]);          \
      H[8]  = ffma2(V, w2.x, H[8]);  H[9]  = ffma2(V, w2.y, H[9]);          \
      H[10] = ffma2(V, w3.x, H[10]); H[11] = ffma2(V, w3.y, H[11]);         \
      H[12] = ffma2(V, w4.x, H[12]); H[13] = ffma2(V, w4.y, H[13]);         \
      H[14] = ffma2(V, w5.x, H[14]); H[15] = ffma2(V, w5.y, H[15]);         \
    }

  // ================= merge head: 48 -> 32 -> 32 -> 2 =================
  u64 h1[16];
  #pragma unroll
  for (int q = 0; q < 16; q++) h1[q] = c2(M_B1 + 2 * q);

  #pragma unroll 2
  for (int t = 0; t < 8; t++) {           // self rows 0..15 (from stash)
    float v0, v1; unpack2(stash_s[t], v0, v1);
    MROW_APPLY(bcast2(v0), M_W1, M_W1S, (2 * t), h1)
    MROW_APPLY(bcast2(v1), M_W1, M_W1S, (2 * t + 1), h1)
  }
  #pragma unroll 2
  for (int t = 0; t < 8; t++) {           // food rows 16..31
    float v0, v1; unpack2(foodp[t], v0, v1);
    MROW_APPLY(bcast2(v0), M_W1, M_W1S, (16 + 2 * t), h1)
    MROW_APPLY(bcast2(v1), M_W1, M_W1S, (16 + 2 * t + 1), h1)
  }
  #pragma unroll 2
  for (int t = 0; t < 8; t++) {           // other rows 32..47 (from stash)
    float v0, v1; unpack2(stash_o[t], v0, v1);
    MROW_APPLY(bcast2(v0), M_W1, M_W1S, (32 + 2 * t), h1)
    MROW_APPLY(bcast2(v1), M_W1, M_W1S, (32 + 2 * t + 1), h1)
  }

  u64 h2[16];
  #pragma unroll
  for (int q = 0; q < 16; q++) h2[q] = c2(M_B2 + 2 * q);
  #pragma unroll 2
  for (int t = 0; t < 16; t++) {
    const u64 v = leaky2(h1[t]);
    float v0, v1; unpack2(v, v0, v1);
    MROW_APPLY(bcast2(v0), M_W2, M_W2S, (2 * t), h2)
    MROW_APPLY(bcast2(v1), M_W2, M_W2S, (2 * t + 1), h2)
  }

  u64 o2 = c2(M_B3);
  #pragma unroll
  for (int t = 0; t < 16; t++) {
    const u64 v = leaky2(h2[t]);
    float v0, v1; unpack2(v, v0, v1);
    o2 = ffma2(bcast2(v0), c2(M_W3 + (2 * t) * 2), o2);
    o2 = ffma2(bcast2(v1), c2(M_W3 + (2 * t + 1) * 2), o2);
  }
  float o0, o1; unpack2(o2, o0, o1);
  float2 res; res.x = tanhf(o0); res.y = tanhf(o1);
  *(float2*)&out[(size_t)b * 2] = res;
}

extern "C" void kernel_launch(void* const* d_in, const int* in_sizes, int n_in,
                              void* d_out, int out_size)
{
  // Gather all weights into the staging blob with ONE kernel, then ONE
  // symbol copy (replaces 22 small memcpy graph nodes).
  pack_weights<<<1, 256>>>(
      (const float*)d_in[1],  (const float*)d_in[2],
      (const float*)d_in[3],  (const float*)d_in[4],
      (const float*)d_in[5],  (const float*)d_in[6],
      (const float*)d_in[7],  (const float*)d_in[8],
      (const float*)d_in[9],  (const float*)d_in[10],
      (const float*)d_in[11], (const float*)d_in[12],
      (const float*)d_in[13], (const float*)d_in[14],
      (const float*)d_in[15], (const float*)d_in[16],
      (const float*)d_in[17], (const float*)d_in[18],
      (const float*)d_in[19], (const float*)d_in[20],
      (const float*)d_in[21], (const float*)d_in[22]);

  void* stage_ptr = nullptr;
  cudaGetSymbolAddress(&stage_ptr, dw_stage);
  cudaMemcpyToSymbolAsync(cw, stage_ptr, CW_TOTAL * sizeof(float), 0,
                          cudaMemcpyDeviceToDevice, 0);

  const float* s = (const float*)d_in[0];
  const int B = in_sizes[0] / OBS;
  const int blocks = (B + THREADS - 1) / THREADS;
  actor_kernel<<<blocks, THREADS>>>(
      s,
      (const float*)d_in[3],   // en_w2
      (const float*)d_in[7],   // oa_w2
      (const float*)d_in[13],  // g_w2
      (const float*)d_in[17],  // m_w1
      (const float*)d_in[19],  // m_w2
      (float*)d_out, B);
}

// round 17
// speedup vs baseline: 1.0550x; 1.0550x over previous
#include <cuda_runtime.h>
#include <math.h>

#define THREADS 128
#define OBS 127

typedef unsigned long long u64;

__device__ __forceinline__ u64 ffma2(u64 a, u64 b, u64 c) {
  u64 d; asm("fma.rn.f32x2 %0, %1, %2, %3;" : "=l"(d) : "l"(a), "l"(b), "l"(c)); return d;
}
__device__ __forceinline__ u64 fmul2(u64 a, u64 b) {
  u64 d; asm("mul.rn.f32x2 %0, %1, %2;" : "=l"(d) : "l"(a), "l"(b)); return d;
}
__device__ __forceinline__ u64 fadd2(u64 a, u64 b) {
  u64 d; asm("add.rn.f32x2 %0, %1, %2;" : "=l"(d) : "l"(a), "l"(b)); return d;
}
__device__ __forceinline__ u64 pack2(float lo, float hi) {
  u64 d; asm("mov.b64 %0, {%1, %2};" : "=l"(d) : "f"(lo), "f"(hi)); return d;
}
__device__ __forceinline__ void unpack2(u64 v, float& lo, float& hi) {
  asm("mov.b64 {%0, %1}, %2;" : "=f"(lo), "=f"(hi) : "l"(v));
}
__device__ __forceinline__ u64 bcast2(float x) { return pack2(x, x); }
__device__ __forceinline__ u64 relu2(u64 v) {
  float a, b; unpack2(v, a, b);
  return pack2(fmaxf(a, 0.0f), fmaxf(b, 0.0f));
}
// leaky_relu(x) = 0.505*x + 0.495*|x| (exact for slope 0.01), packed.
__device__ __forceinline__ u64 leaky2(u64 v) {
  const u64 absv = v & 0x7FFFFFFF7FFFFFFFULL;
  return ffma2(bcast2(0.505f), v, fmul2(bcast2(0.495f), absv));
}

// ---------------- constant blob: raw tensor layouts (float offsets) ----------------
enum {
  EN_W1 = 0,      // [4][32]
  EN_B1 = 128,    // [32]
  EN_W2 = 160,    // [32][16]
  EN_B2 = 672,    // [16]
  OA_W1 = 688,    // [5][32]
  OA_B1 = 848,    // [32]
  OA_W2 = 880,    // [32][16]
  OA_B2 = 1392,   // [16]
  OA_G  = 1408,   // [16]
  OA_BLN= 1424,   // [16]
  G_W1  = 1440,   // [3][32]
  G_B1  = 1536,   // [32]
  G_W2  = 1568,   // [32][16]
  G_B2  = 2080,   // [16]
  G_G   = 2096,   // [16]
  G_BLN = 2112,   // [16]
  M_W1  = 2128,   // [48][32]
  M_B1  = 3664,   // [32]
  M_W2  = 3696,   // [32][32]
  M_B2  = 4720,   // [32]
  M_W3  = 4752,   // [32][2]
  M_B3  = 4816,   // [2]
  CW_TOTAL = 4818
};
__constant__ float cw[CW_TOTAL];
__device__ float dw_stage[CW_TOTAL];      // staging for single-symbol-copy upload
__device__ __forceinline__ u64 c2(int off) { return *(const u64*)(cw + off); }

// Gather all 22 weight tensors into the staging blob in one kernel.
__global__ void pack_weights(
    const float* p1,  const float* p2,  const float* p3,  const float* p4,
    const float* p5,  const float* p6,  const float* p7,  const float* p8,
    const float* p9,  const float* p10, const float* p11, const float* p12,
    const float* p13, const float* p14, const float* p15, const float* p16,
    const float* p17, const float* p18, const float* p19, const float* p20,
    const float* p21, const float* p22)
{
  const int t = threadIdx.x;
  #define SEG(off, src, n) for (int i = t; i < (n); i += 256) dw_stage[(off) + i] = (src)[i];
  SEG(EN_W1, p1, 128)  SEG(EN_B1, p2, 32)
  SEG(EN_W2, p3, 512)  SEG(EN_B2, p4, 16)
  SEG(OA_W1, p5, 160)  SEG(OA_B1, p6, 32)
  SEG(OA_W2, p7, 512)  SEG(OA_B2, p8, 16)
  SEG(OA_G,  p9, 16)   SEG(OA_BLN, p10, 16)
  SEG(G_W1,  p11, 96)  SEG(G_B1, p12, 32)
  SEG(G_W2,  p13, 512) SEG(G_B2, p14, 16)
  SEG(G_G,   p15, 16)  SEG(G_BLN, p16, 16)
  SEG(M_W1,  p17, 1536) SEG(M_B1, p18, 32)
  SEG(M_W2,  p19, 1024) SEG(M_B2, p20, 32)
  SEG(M_W3,  p21, 64)  SEG(M_B3, p22, 2)
  #undef SEG
}

// ---------------- smem: high-column weight mirror + per-thread otherp stash ----------------
enum {
  EN_W2S = 0,     // [32][16]
  OA_W2S = 512,   // [32][16]
  G_W2S  = 1024,  // [32][16]
  M_W1S  = 1536,  // [48][32]
  M_W2S  = 3072,  // [32][32]
  STASH  = 4096,  // 128 threads * 16 floats (8 u64)
  SW_TOTAL = 4096 + THREADS * 16
};

__global__ void __launch_bounds__(THREADS, 5)
actor_kernel(const float* __restrict__ s_input,
             const float* __restrict__ en_w2g, const float* __restrict__ oa_w2g,
             const float* __restrict__ g_w2g,  const float* __restrict__ m_w1g,
             const float* __restrict__ m_w2g,
             float* __restrict__ out, int B)
{
  __shared__ float sw[SW_TOTAL];
  const int tid = threadIdx.x;
  #define CP(off, src, n) \
    for (int i = tid; i < (n); i += THREADS) sw[(off) + i] = (src)[i];
  CP(EN_W2S, en_w2g, 512)
  CP(OA_W2S, oa_w2g, 512)
  CP(G_W2S,  g_w2g,  512)
  CP(M_W1S,  m_w1g,  1536)
  CP(M_W2S,  m_w2g,  1024)
  #undef CP
  __syncthreads();

  const int b = blockIdx.x * THREADS + tid;
  if (b >= B) return;
  const float* __restrict__ s = s_input + (size_t)b * OBS;
  u64* const stash = (u64*)&sw[STASH + tid * 16];

  // Layer-2 row apply, SINGLE entity: cols 0..3 const, 4..15 smem.
  #define L2ROW1(A, CBASE, SBASE, ROW)                                      \
    {                                                                       \
      ea[0] = ffma2(A, c2((CBASE) + (ROW) * 16 + 0), ea[0]);                \
      ea[1] = ffma2(A, c2((CBASE) + (ROW) * 16 + 2), ea[1]);                \
      const ulonglong2* wh = (const ulonglong2*)&sw[(SBASE) + (ROW) * 16 + 4]; \
      ulonglong2 v0 = wh[0], v1 = wh[1], v2 = wh[2];                        \
      ea[2] = ffma2(A, v0.x, ea[2]); ea[3] = ffma2(A, v0.y, ea[3]);         \
      ea[4] = ffma2(A, v1.x, ea[4]); ea[5] = ffma2(A, v1.y, ea[5]);         \
      ea[6] = ffma2(A, v2.x, ea[6]); ea[7] = ffma2(A, v2.y, ea[7]);         \
    }

  // Layer-2 row apply, PAIR of entities: weights fetched ONCE, applied twice.
  #define L2ROW2(Aa, Ab, CBASE, SBASE, ROW)                                 \
    {                                                                       \
      u64 cwa = c2((CBASE) + (ROW) * 16 + 0), cwb = c2((CBASE) + (ROW) * 16 + 2); \
      ea[0] = ffma2(Aa, cwa, ea[0]); eb[0] = ffma2(Ab, cwa, eb[0]);         \
      ea[1] = ffma2(Aa, cwb, ea[1]); eb[1] = ffma2(Ab, cwb, eb[1]);         \
      const ulonglong2* wh = (const ulonglong2*)&sw[(SBASE) + (ROW) * 16 + 4]; \
      ulonglong2 v0 = wh[0], v1 = wh[1], v2 = wh[2];                        \
      ea[2] = ffma2(Aa, v0.x, ea[2]); eb[2] = ffma2(Ab, v0.x, eb[2]);       \
      ea[3] = ffma2(Aa, v0.y, ea[3]); eb[3] = ffma2(Ab, v0.y, eb[3]);       \
      ea[4] = ffma2(Aa, v1.x, ea[4]); eb[4] = ffma2(Ab, v1.x, eb[4]);       \
      ea[5] = ffma2(Aa, v1.y, ea[5]); eb[5] = ffma2(Ab, v1.y, eb[5]);       \
      ea[6] = ffma2(Aa, v2.x, ea[6]); eb[6] = ffma2(Ab, v2.x, eb[6]);       \
      ea[7] = ffma2(Aa, v2.y, ea[7]); eb[7] = ffma2(Ab, v2.y, eb[7]);       \
    }

  // Single-entity softmax update (loop tails).
  #define SM_UPDATE(earr)                                                   \
    {                                                                       \
      _Pragma("unroll")                                                     \
      for (int t = 0; t < 8; t++) earr[t] = relu2(earr[t]);                 \
      u64 sc2a = 0ULL, sc2b = 0ULL;                                         \
      _Pragma("unroll")                                                     \
      for (int t = 0; t < 4; t++) {                                         \
        sc2a = ffma2(selfp[2*t],     earr[2*t],     sc2a);                  \
        sc2b = ffma2(selfp[2*t + 1], earr[2*t + 1], sc2b);                  \
      }                                                                     \
      const u64 sc2 = fadd2(sc2a, sc2b);                                    \
      float slo, shi; unpack2(sc2, slo, shi);                               \
      const float pe = __expf((slo + shi) * 0.25f);                         \
      dd += pe;                                                             \
      const u64 P = bcast2(pe);                                             \
      _Pragma("unroll")                                                     \
      for (int t = 0; t < 8; t++) acc[t] = ffma2(P, earr[t], acc[t]);       \
    }

  // FUSED pair softmax update: both score dots in parallel chains, both
  // MUFU exps issued back-to-back (latencies overlap), merged acc update.
  #define SM_UPDATE2(ea, eb)                                                \
    {                                                                       \
      _Pragma("unroll")                                                     \
      for (int t = 0; t < 8; t++) { ea[t] = relu2(ea[t]); eb[t] = relu2(eb[t]); } \
      u64 sa0 = 0ULL, sa1 = 0ULL, sb0 = 0ULL, sb1 = 0ULL;                   \
      _Pragma("unroll")                                                     \
      for (int t = 0; t < 4; t++) {                                         \
        sa0 = ffma2(selfp[2*t],     ea[2*t],     sa0);                      \
        sa1 = ffma2(selfp[2*t + 1], ea[2*t + 1], sa1);                      \
        sb0 = ffma2(selfp[2*t],     eb[2*t],     sb0);                      \
        sb1 = ffma2(selfp[2*t + 1], eb[2*t + 1], sb1);                      \
      }                                                                     \
      const u64 sca = fadd2(sa0, sa1), scb = fadd2(sb0, sb1);               \
      float alo, ahi, blo, bhi;                                             \
      unpack2(sca, alo, ahi); unpack2(scb, blo, bhi);                       \
      const float pa = __expf((alo + ahi) * 0.25f);                         \
      const float pb = __expf((blo + bhi) * 0.25f);                         \
      dd += pa; dd += pb;                                                   \
      const u64 Pa = bcast2(pa), Pb = bcast2(pb);                           \
      _Pragma("unroll")                                                     \
      for (int t = 0; t < 8; t++)                                           \
        acc[t] = ffma2(Pb, eb[t], ffma2(Pa, ea[t], acc[t]));                \
    }

  // LayerNorm + relu epilogue from acc/dd into dst.
  #define LN_EPILOGUE(dst, GOFF, BLNOFF)                                    \
    {                                                                       \
      const u64 INV = bcast2(1.0f / dd);                                    \
      float att[16], mu = 0.0f;                                             \
      _Pragma("unroll")                                                     \
      for (int t = 0; t < 8; t++) {                                         \
        acc[t] = fmul2(acc[t], INV);                                        \
        float a0, a1; unpack2(acc[t], a0, a1);                              \
        att[2*t] = a0; att[2*t+1] = a1;                                     \
        mu += a0 + a1;                                                      \
      }                                                                     \
      mu *= (1.0f / 16.0f);                                                 \
      float var = 0.0f;                                                     \
      _Pragma("unroll")                                                     \
      for (int k = 0; k < 16; k++) { const float t = att[k] - mu; var = fmaf(t, t, var); } \
      var *= (1.0f / 16.0f);                                                \
      const float isd = rsqrtf(var + 1e-5f);                                \
      _Pragma("unroll")                                                     \
      for (int t = 0; t < 8; t++) {                                         \
        const u64 y = pack2((att[2*t] - mu) * isd, (att[2*t+1] - mu) * isd);\
        dst[t] = relu2(ffma2(y, c2((GOFF) + 2*t), c2((BLNOFF) + 2*t)));     \
      }                                                                     \
    }

  // ================= self MLP: 4 -> 32 -> 16 =================
  u64 selfp[8];
  {
    u64 ea[8];
    #pragma unroll
    for (int t = 0; t < 8; t++) ea[t] = c2(EN_B2 + 2 * t);
    const u64 p0 = bcast2(s[0]), p1 = bcast2(s[1]), p2 = bcast2(s[2]), p3 = bcast2(s[3]);
    #pragma unroll 4
    for (int jp = 0; jp < 16; jp++) {
      u64 a = c2(EN_B1 + 2 * jp);
      a = ffma2(p0, c2(EN_W1 +      2 * jp), a);
      a = ffma2(p1, c2(EN_W1 + 32 + 2 * jp), a);
      a = ffma2(p2, c2(EN_W1 + 64 + 2 * jp), a);
      a = ffma2(p3, c2(EN_W1 + 96 + 2 * jp), a);
      float a0, a1; unpack2(a, a0, a1);
      const u64 A0 = bcast2(fmaxf(a0, 0.0f));
      const u64 A1 = bcast2(fmaxf(a1, 0.0f));
      L2ROW1(A0, EN_W2, EN_W2S, 2 * jp)
      L2ROW1(A1, EN_W2, EN_W2S, 2 * jp + 1)
    }
    #pragma unroll
    for (int t = 0; t < 8; t++) selfp[t] = relu2(ea[t]);
  }

  // ================= other-agent branch: 15 entities = 7 pairs + 1 =================
  {
    float dd = 0.0f;
    u64 acc[8];
    #pragma unroll
    for (int t = 0; t < 8; t++) acc[t] = 0ULL;

    #pragma unroll 1
    for (int q = 0; q < 7; q++) {
      const int n = 2 * q;
      const u64 pa0 = bcast2(s[4 + 2*n]),  pb0 = bcast2(s[6 + 2*n]);
      const u64 pa1 = bcast2(s[5 + 2*n]),  pb1 = bcast2(s[7 + 2*n]);
      const u64 pa2 = bcast2(s[34 + 2*n]), pb2 = bcast2(s[36 + 2*n]);
      const u64 pa3 = bcast2(s[35 + 2*n]), pb3 = bcast2(s[37 + 2*n]);
      const u64 pa4 = bcast2(s[64 + n]),   pb4 = bcast2(s[65 + n]);

      u64 ea[8], eb[8];
      #pragma unroll
      for (int t = 0; t < 8; t++) { u64 bb = c2(OA_B2 + 2 * t); ea[t] = bb; eb[t] = bb; }

      #pragma unroll 2
      for (int jp = 0; jp < 16; jp++) {
        const u64 kb = c2(OA_B1 + 2 * jp);
        const u64 k0 = c2(OA_W1 +       2 * jp);
        const u64 k1 = c2(OA_W1 + 32  + 2 * jp);
        const u64 k2 = c2(OA_W1 + 64  + 2 * jp);
        const u64 k3 = c2(OA_W1 + 96  + 2 * jp);
        const u64 k4 = c2(OA_W1 + 128 + 2 * jp);
        u64 aa = kb;
        aa = ffma2(pa0, k0, aa); aa = ffma2(pa1, k1, aa); aa = ffma2(pa2, k2, aa);
        aa = ffma2(pa3, k3, aa); aa = ffma2(pa4, k4, aa);
        u64 ab = kb;
        ab = ffma2(pb0, k0, ab); ab = ffma2(pb1, k1, ab); ab = ffma2(pb2, k2, ab);
        ab = ffma2(pb3, k3, ab); ab = ffma2(pb4, k4, ab);
        float x0, x1; unpack2(aa, x0, x1);
        const u64 Aa0 = bcast2(fmaxf(x0, 0.0f));
        const u64 Aa1 = bcast2(fmaxf(x1, 0.0f));
        unpack2(ab, x0, x1);
        const u64 Ab0 = bcast2(fmaxf(x0, 0.0f));
        const u64 Ab1 = bcast2(fmaxf(x1, 0.0f));
        L2ROW2(Aa0, Ab0, OA_W2, OA_W2S, 2 * jp)
        L2ROW2(Aa1, Ab1, OA_W2, OA_W2S, 2 * jp + 1)
      }
      SM_UPDATE2(ea, eb)
    }
    { // tail entity n = 14
      const int n = 14;
      const u64 p0 = bcast2(s[4 + 2*n]);
      const u64 p1 = bcast2(s[5 + 2*n]);
      const u64 p2 = bcast2(s[34 + 2*n]);
      const u64 p3 = bcast2(s[35 + 2*n]);
      const u64 p4 = bcast2(s[64 + n]);
      u64 ea[8];
      #pragma unroll
      for (int t = 0; t < 8; t++) ea[t] = c2(OA_B2 + 2 * t);
      #pragma unroll 2
      for (int jp = 0; jp < 16; jp++) {
        u64 a = c2(OA_B1 + 2 * jp);
        a = ffma2(p0, c2(OA_W1 +       2 * jp), a);
        a = ffma2(p1, c2(OA_W1 + 32  + 2 * jp), a);
        a = ffma2(p2, c2(OA_W1 + 64  + 2 * jp), a);
        a = ffma2(p3, c2(OA_W1 + 96  + 2 * jp), a);
        a = ffma2(p4, c2(OA_W1 + 128 + 2 * jp), a);
        float x0, x1; unpack2(a, x0, x1);
        const u64 A0 = bcast2(fmaxf(x0, 0.0f));
        const u64 A1 = bcast2(fmaxf(x1, 0.0f));
        L2ROW1(A0, OA_W2, OA_W2S, 2 * jp)
        L2ROW1(A1, OA_W2, OA_W2S, 2 * jp + 1)
      }
      SM_UPDATE(ea)
    }
    u64 otherp[8];
    LN_EPILOGUE(otherp, OA_G, OA_BLN)
    #pragma unroll
    for (int t = 0; t < 8; t++) stash[t] = otherp[t];   // free 16 regs for food loop
  }

  // ================= food branch: 16 entities = 8 pairs =================
  u64 foodp[8];
  {
    float dd = 0.0f;
    u64 acc[8];
    #pragma unroll
    for (int t = 0; t < 8; t++) acc[t] = 0ULL;

    #pragma unroll 1
    for (int q = 0; q < 8; q++) {
      const int n = 2 * q;
      const u64 pa0 = bcast2(s[79 + 3*n]), pb0 = bcast2(s[82 + 3*n]);
      const u64 pa1 = bcast2(s[80 + 3*n]), pb1 = bcast2(s[83 + 3*n]);
      const u64 pa2 = bcast2(s[81 + 3*n]), pb2 = bcast2(s[84 + 3*n]);

      u64 ea[8], eb[8];
      #pragma unroll
      for (int t = 0; t < 8; t++) { u64 bb = c2(G_B2 + 2 * t); ea[t] = bb; eb[t] = bb; }

      #pragma unroll 2
      for (int jp = 0; jp < 16; jp++) {
        const u64 kb = c2(G_B1 + 2 * jp);
        const u64 k0 = c2(G_W1 +      2 * jp);
        const u64 k1 = c2(G_W1 + 32 + 2 * jp);
        const u64 k2 = c2(G_W1 + 64 + 2 * jp);
        u64 aa = kb;
        aa = ffma2(pa0, k0, aa); aa = ffma2(pa1, k1, aa); aa = ffma2(pa2, k2, aa);
        u64 ab = kb;
        ab = ffma2(pb0, k0, ab); ab = ffma2(pb1, k1, ab); ab = ffma2(pb2, k2, ab);
        float x0, x1; unpack2(aa, x0, x1);
        const u64 Aa0 = bcast2(fmaxf(x0, 0.0f));
        const u64 Aa1 = bcast2(fmaxf(x1, 0.0f));
        unpack2(ab, x0, x1);
        const u64 Ab0 = bcast2(fmaxf(x0, 0.0f));
        const u64 Ab1 = bcast2(fmaxf(x1, 0.0f));
        L2ROW2(Aa0, Ab0, G_W2, G_W2S, 2 * jp)
        L2ROW2(Aa1, Ab1, G_W2, G_W2S, 2 * jp + 1)
      }
      SM_UPDATE2(ea, eb)
    }
    LN_EPILOGUE(foodp, G_G, G_BLN)
  }

  // Merge-layer row apply: outputs 0..7 const, outputs 8..31 smem.
  #define MROW_APPLY(V, CBASE, SBASE, ROW, H)                               \
    {                                                                       \
      H[0] = ffma2(V, c2((CBASE) + (ROW) * 32 + 0), H[0]);                  \
      H[1] = ffma2(V, c2((CBASE) + (ROW) * 32 + 2), H[1]);                  \
      H[2] = ffma2(V, c2((CBASE) + (ROW) * 32 + 4), H[2]);                  \
      H[3] = ffma2(V, c2((CBASE) + (ROW) * 32 + 6), H[3]);                  \
      const ulonglong2* wh = (const ulonglong2*)&sw[(SBASE) + (ROW) * 32 + 8]; \
      ulonglong2 w0 = wh[0], w1 = wh[1], w2 = wh[2],                        \
                 w3 = wh[3], w4 = wh[4], w5 = wh[5];                        \
      H[4]  = ffma2(V, w0.x, H[4]);  H[5]  = ffma2(V, w0.y, H[5]);          \
      H[6]  = ffma2(V, w1.x, H[6]);  H[7]  = ffma2(V, w1.y, H[7]);          \
      H[8]  = ffma2(V, w2.x, H[8]);  H[9]  = ffma2(V, w2.y, H[9]);          \
      H[10] = ffma2(V, w3.x, H[10]); H[11] = ffma2(V, w3.y, H[11]);         \
      H[12] = ffma2(V, w4.x, H[12]); H[13] = ffma2(V, w4.y, H[13]);         \
      H[14] = ffma2(V, w5.x, H[14]); H[15] = ffma2(V, w5.y, H[15]);         \
    }

  // ================= merge head: 48 -> 32 -> 32 -> 2 =================
  u64 h1[16];
  #pragma unroll
  for (int q = 0; q < 16; q++) h1[q] = c2(M_B1 + 2 * q);

  #pragma unroll 2
  for (int t = 0; t < 8; t++) {           // self rows 0..15
    float v0, v1; unpack2(selfp[t], v0, v1);
    MROW_APPLY(bcast2(v0), M_W1, M_W1S, (2 * t), h1)
    MROW_APPLY(bcast2(v1), M_W1, M_W1S, (2 * t + 1), h1)
  }
  #pragma unroll 2
  for (int t = 0; t < 8; t++) {           // food rows 16..31
    float v0, v1; unpack2(foodp[t], v0, v1);
    MROW_APPLY(bcast2(v0), M_W1, M_W1S, (16 + 2 * t), h1)
    MROW_APPLY(bcast2(v1), M_W1, M_W1S, (16 + 2 * t + 1), h1)
  }
  #pragma unroll 2
  for (int t = 0; t < 8; t++) {           // other rows 32..47 (from stash)
    float v0, v1; unpack2(stash[t], v0, v1);
    MROW_APPLY(bcast2(v0), M_W1, M_W1S, (32 + 2 * t), h1)
    MROW_APPLY(bcast2(v1), M_W1, M_W1S, (32 + 2 * t + 1), h1)
  }

  u64 h2[16];
  #pragma unroll
  for (int q = 0; q < 16; q++) h2[q] = c2(M_B2 + 2 * q);
  #pragma unroll 2
  for (int t = 0; t < 16; t++) {
    const u64 v = leaky2(h1[t]);
    float v0, v1; unpack2(v, v0, v1);
    MROW_APPLY(bcast2(v0), M_W2, M_W2S, (2 * t), h2)
    MROW_APPLY(bcast2(v1), M_W2, M_W2S, (2 * t + 1), h2)
  }

  u64 o2 = c2(M_B3);
  #pragma unroll
  for (int t = 0; t < 16; t++) {
    const u64 v = leaky2(h2[t]);
    float v0, v1; unpack2(v, v0, v1);
    o2 = ffma2(bcast2(v0), c2(M_W3 + (2 * t) * 2), o2);
    o2 = ffma2(bcast2(v1), c2(M_W3 + (2 * t + 1) * 2), o2);
  }
  float o0, o1; unpack2(o2, o0, o1);
  float2 res; res.x = tanhf(o0); res.y = tanhf(o1);
  *(float2*)&out[(size_t)b * 2] = res;
}

extern "C" void kernel_launch(void* const* d_in, const int* in_sizes, int n_in,
                              void* d_out, int out_size)
{
  // Gather all weights into the staging blob with ONE kernel, then ONE
  // symbol copy (replaces 22 small memcpy graph nodes).
  pack_weights<<<1, 256>>>(
      (const float*)d_in[1],  (const float*)d_in[2],
      (const float*)d_in[3],  (const float*)d_in[4],
      (const float*)d_in[5],  (const float*)d_in[6],
      (const float*)d_in[7],  (const float*)d_in[8],
      (const float*)d_in[9],  (const float*)d_in[10],
      (const float*)d_in[11], (const float*)d_in[12],
      (const float*)d_in[13], (const float*)d_in[14],
      (const float*)d_in[15], (const float*)d_in[16],
      (const float*)d_in[17], (const float*)d_in[18],
      (const float*)d_in[19], (const float*)d_in[20],
      (const float*)d_in[21], (const float*)d_in[22]);

  void* stage_ptr = nullptr;
  cudaGetSymbolAddress(&stage_ptr, dw_stage);
  cudaMemcpyToSymbolAsync(cw, stage_ptr, CW_TOTAL * sizeof(float), 0,
                          cudaMemcpyDeviceToDevice, 0);

  const float* s = (const float*)d_in[0];
  const int B = in_sizes[0] / OBS;
  const int blocks = (B + THREADS - 1) / THREADS;
  actor_kernel<<<blocks, THREADS>>>(
      s,
      (const float*)d_in[3],   // en_w2
      (const float*)d_in[7],   // oa_w2
      (const float*)d_in[13],  // g_w2
      (const float*)d_in[17],  // m_w1
      (const float*)d_in[19],  // m_w2
      (float*)d_out, B);
}